// round 10
// baseline (speedup 1.0000x reference)
#include <cuda_runtime.h>
#include <cuda_bf16.h>

#define B_ 512
#define T_ 512
#define N_ 64

#define L2E 1.4426950408889634f   // log2(e)
#define LN2 0.6931471805599453f   // ln(2)
#define MAGICF 12582912.0f        // 1.5 * 2^23 (round-to-int magic)

// 2^f Taylor/minimax coefficients on [-0.5, 0.5] (degree 4, rel err ~3e-5)
#define C1 0.6931471806f
#define C2 0.2402265070f
#define C3 0.0555041087f
#define C4 0.0096181291f

// ---- packed f32x2 + MUFU helpers (sm_103a) ----
__device__ __forceinline__ void ffma2(unsigned long long &d,
                                      unsigned long long a,
                                      unsigned long long b) {
    asm("fma.rn.f32x2 %0, %1, %2, %0;" : "+l"(d) : "l"(a), "l"(b));
}
__device__ __forceinline__ unsigned long long fadd2(unsigned long long a,
                                                    unsigned long long b) {
    unsigned long long d;
    asm("add.rn.f32x2 %0, %1, %2;" : "=l"(d) : "l"(a), "l"(b));
    return d;
}
__device__ __forceinline__ unsigned long long pack2(float lo, float hi) {
    unsigned long long d;
    asm("mov.b64 %0, {%1, %2};" : "=l"(d) : "f"(lo), "f"(hi));
    return d;
}
__device__ __forceinline__ void unpack2(unsigned long long v, float &lo, float &hi) {
    asm("mov.b64 {%0, %1}, %2;" : "=f"(lo), "=f"(hi) : "l"(v));
}
__device__ __forceinline__ float ex2(float x) {
    float r; asm("ex2.approx.f32 %0, %1;" : "=f"(r) : "f"(x)); return r;
}
__device__ __forceinline__ float lg2(float x) {
    float r; asm("lg2.approx.f32 %0, %1;" : "=f"(r) : "f"(x)); return r;
}
__device__ __forceinline__ void gbar(int id) {
    asm volatile("bar.sync %0, 64;" :: "r"(id) : "memory");
}

// Polynomial exp2 of (e * L2E) on the FMA/ALU pipes (NO MUFU).
// Magic-add range reduction (exact n, exact f), degree-4 Estrin, exact
// exponent-bit scale. Valid for |e*L2E| < ~60; rel err ~3e-5.
__device__ __forceinline__ float exp2_poly(float e) {
    const float xK = fmaf(e, L2E, MAGICF);        // low bits hold round(x)
    const float nf = xK - MAGICF;                 // n as float (exact)
    const float f  = fmaf(e, L2E, -nf);           // f in [-0.5, 0.5] (exact)
    const float f2 = f * f;
    const float pA = fmaf(f, C1, 1.0f);
    const float pB = fmaf(f, C3, C2);
    const float pC = fmaf(f2, C4, pB);
    const float p  = fmaf(f2, pC, pA);            // 2^f
    // scale by 2^n: add n (low bits of xK) into the exponent field, exact
    // (mod-2^32 wrap handles negative n).
    return __uint_as_float(__float_as_uint(p) + (__float_as_uint(xK) << 23));
}

// Full 64-MAC column GEMV: s = sum_i v[i] * ET[i], packed f32x2,
// 16 broadcast LDS.128 + 32 FFMA2, 8 accumulators (depth 4).
__device__ __forceinline__ float gemv64(const float* __restrict__ vsrc,
                                        const unsigned long long* __restrict__ ETp) {
    const ulonglong2* ev = reinterpret_cast<const ulonglong2*>(vsrc);
    unsigned long long a0 = 0ull, a1 = 0ull, a2 = 0ull, a3 = 0ull;
    unsigned long long a4 = 0ull, a5 = 0ull, a6 = 0ull, a7 = 0ull;
#pragma unroll
    for (int m = 0; m < 4; m++) {
        const ulonglong2 p0 = ev[4 * m + 0];
        const ulonglong2 p1 = ev[4 * m + 1];
        const ulonglong2 p2 = ev[4 * m + 2];
        const ulonglong2 p3 = ev[4 * m + 3];
        ffma2(a0, p0.x, ETp[8 * m + 0]);
        ffma2(a1, p0.y, ETp[8 * m + 1]);
        ffma2(a2, p1.x, ETp[8 * m + 2]);
        ffma2(a3, p1.y, ETp[8 * m + 3]);
        ffma2(a4, p2.x, ETp[8 * m + 4]);
        ffma2(a5, p2.y, ETp[8 * m + 5]);
        ffma2(a6, p3.x, ETp[8 * m + 6]);
        ffma2(a7, p3.y, ETp[8 * m + 7]);
    }
    const unsigned long long sA =
        fadd2(fadd2(fadd2(a0, a1), fadd2(a2, a3)),
              fadd2(fadd2(a4, a5), fadd2(a6, a7)));
    float slo, shi;
    unpack2(sA, slo, shi);
    return slo + shi;
}

// FORWARD-BACKWARD split, 2-warp gangs (round-9 structure), with the emission
// exponential load-balanced across hardware units:
//   step A: ms = MUFU ex2(emit*L2E - q)   (q rescale folded into the arg)
//   step B: ms = exp2_poly(emit)          (FMA/ALU pipes, zero MUFU)
// This halves per-step MUFU pressure (the measured bottleneck: 8.4M ex2 *
// rt8 = ~60us of full-chip MUFU) at +7 cheap fixed-lat ops every other step.
__global__ __launch_bounds__(128) void crf_fb(
    const float* __restrict__ inputs,   // [B, T, N]
    const float* __restrict__ trans,    // [N, N]
    const int*   __restrict__ tags,     // [B, T]
    const int*   __restrict__ lens,     // [B]
    float*       __restrict__ out)      // [B + N*N]
{
    const int b    = blockIdx.x;
    const int tid  = threadIdx.x;
    const int grp  = tid >> 6;                 // 0 = forward, 1 = backward
    const int gt   = tid & 63;                 // owned column / row index
    const int barid = grp + 1;

    __shared__ __align__(16) float Esh[2][2][68];   // [group][buf][vec]
    __shared__ float Rsh[2];
    __shared__ float redD[2];
    __shared__ float redS[4];

    // Passthrough copy of transition_params (512 blocks x 8 elems = 4096).
    if (tid < 8) {
        const int idx = b * 8 + tid;
        out[B_ + idx] = trans[idx];
    }

    // Register matrix, packed over the contraction index i:
    //   gang 0 (fwd): ET[i] = exp2(trans[i][gt] * L2E)   (A^T column gt)
    //   gang 1 (bwd): ET[i] = exp2(trans[gt][i] * L2E)   (A row gt)
    unsigned long long ETp[32];
#pragma unroll
    for (int m = 0; m < 32; m++) {
        const int ia = grp ? (gt * N_ + 2 * m)     : ((2 * m) * N_ + gt);
        const int ib = grp ? (gt * N_ + 2 * m + 1) : ((2 * m + 1) * N_ + gt);
        ETp[m] = pack2(ex2(trans[ia] * L2E), ex2(trans[ib] * L2E));
    }

    const float* emit = inputs + (size_t)b * T_ * N_;
    const int len = lens[b];
    const int L = (len > 1) ? (len - 1) : 0;   // last alpha index
    const int fsteps = L >> 1;                 // forward GEMV count (mid = fsteps)
    const int ns = grp ? (L - fsteps) : fsteps;   // my GEMV count
    const int ne = grp ? (ns - 1) : ns;        // last k with a real emission
    const int st = grp ? L : 0;                // emission row at k=0
    const int dr = grp ? -1 : 1;               // row direction

    float (*V)[68] = Esh[grp];                 // my double buffer

    // Init vector into V[0] (+ my accumulated log2 shift R).
    float R;
    if (grp == 0) {
        const float r0 = __ldg(&emit[0]) * L2E;
        R = r0;
        V[0][gt] = ex2(fmaf(emit[gt], L2E, -r0));
    } else if (ns > 0) {
        const float r0 = __ldg(&emit[(size_t)L * N_]) * L2E;
        R = r0;
        V[0][gt] = ex2(fmaf(emit[(size_t)L * N_ + gt], L2E, -r0));
    } else {
        R = 0.0f;
        V[0][gt] = 1.0f;                       // beta = ones when no bwd steps
    }

    // Emission prefetch for my column, one unrolled pair ahead.
    float ecA = (1 <= ne) ? emit[(st + dr) * N_ + gt] : 0.0f;
    float ecB = (2 <= ne) ? emit[(st + 2 * dr) * N_ + gt] : 0.0f;

    gbar(barid);

    int k = 1;
    for (; k + 1 <= ns; k += 2) {
        const float eA = (k + 2 <= ne) ? emit[(st + dr * (k + 2)) * N_ + gt] : 0.0f;
        const float eB = (k + 3 <= ne) ? emit[(st + dr * (k + 3)) * N_ + gt] : 0.0f;

        // ---- step A (rescaled, MUFU ex2): V[0] -> V[1] ----
        {
            const float E0 = V[0][0];
            const float q = (float)((int)((__float_as_uint(E0) >> 23) & 0xFF) - 121);
            const float ms = ex2(fmaf(ecA, L2E, -q));
            R += q;
            const float s = gemv64(&V[0][0], ETp);
            V[1][gt] = ms * s;
            gbar(barid);
        }

        // ---- step B (no rescale, POLY exp2 -- zero MUFU): V[1] -> V[0] ----
        {
            const float ms = exp2_poly(ecB);
            const float s = gemv64(&V[1][0], ETp);
            V[0][gt] = ms * s;
            gbar(barid);
        }

        ecA = eA;
        ecB = eB;
    }

    // Odd leftover step (k == ns): rescaled, V[0] -> V[1].
    if (k <= ns) {
        const float E0 = V[0][0];
        const float q = (float)((int)((__float_as_uint(E0) >> 23) & 0xFF) - 121);
        const float ms = ex2(fmaf(ecA, L2E, -q));
        R += q;
        const float s = gemv64(&V[0][0], ETp);
        V[1][gt] = ms * s;
        gbar(barid);
    }

    // ---- join: Z = sum_i v_mid[i] * beta_mid[i] ----
    if (gt == 0) Rsh[grp] = R;
    __syncthreads();

    const int fpar = fsteps & 1;
    const int bpar = (L - fsteps) & 1;
    float dv = (tid < 64) ? Esh[0][fpar][tid] * Esh[1][bpar][tid] : 0.0f;
#pragma unroll
    for (int off = 16; off; off >>= 1)
        dv += __shfl_xor_sync(0xffffffffu, dv, off);
    if (tid < 64 && (tid & 31) == 0) redD[tid >> 5] = dv;

    // Sequence score over all 128 threads: unary [0,len), binary [1,len).
    const int* btags = tags + b * T_;
    float sc = 0.0f;
    for (int q = tid; q < len; q += 128)
        sc += emit[q * N_ + btags[q]];
    for (int q = tid + 1; q < len; q += 128)
        sc += trans[btags[q - 1] * N_ + btags[q]];
#pragma unroll
    for (int off = 16; off; off >>= 1)
        sc += __shfl_xor_sync(0xffffffffu, sc, off);
    if ((tid & 31) == 0) redS[tid >> 5] = sc;
    __syncthreads();

    if (tid == 0) {
        const float logZ = (Rsh[0] + Rsh[1] + lg2(redD[0] + redD[1])) * LN2;
        out[b] = ((redS[0] + redS[1]) + (redS[2] + redS[3])) - logZ;
    }
}

extern "C" void kernel_launch(void* const* d_in, const int* in_sizes, int n_in,
                              void* d_out, int out_size) {
    const float* inputs = (const float*)d_in[0];   // [512, 512, 64] f32
    const float* trans  = (const float*)d_in[1];   // [64, 64] f32
    const int*   tags   = (const int*)d_in[2];     // [512, 512] i32
    const int*   lens   = (const int*)d_in[3];     // [512] i32
    float*       out    = (float*)d_out;           // [512 + 4096] f32

    crf_fb<<<B_, 128>>>(inputs, trans, tags, lens, out);
}

// round 11
// speedup vs baseline: 1.0294x; 1.0294x over previous
#include <cuda_runtime.h>
#include <cuda_bf16.h>

#define B_ 512
#define T_ 512
#define N_ 64

#define L2E 1.4426950408889634f   // log2(e)
#define LN2 0.6931471805599453f   // ln(2)

// ---- packed f32x2 + MUFU helpers (sm_103a) ----
__device__ __forceinline__ void ffma2(unsigned long long &d,
                                      unsigned long long a,
                                      unsigned long long b) {
    asm("fma.rn.f32x2 %0, %1, %2, %0;" : "+l"(d) : "l"(a), "l"(b));
}
__device__ __forceinline__ unsigned long long fadd2(unsigned long long a,
                                                    unsigned long long b) {
    unsigned long long d;
    asm("add.rn.f32x2 %0, %1, %2;" : "=l"(d) : "l"(a), "l"(b));
    return d;
}
__device__ __forceinline__ unsigned long long pack2(float lo, float hi) {
    unsigned long long d;
    asm("mov.b64 %0, {%1, %2};" : "=l"(d) : "f"(lo), "f"(hi));
    return d;
}
__device__ __forceinline__ void unpack2(unsigned long long v, float &lo, float &hi) {
    asm("mov.b64 {%0, %1}, %2;" : "=f"(lo), "=f"(hi) : "l"(v));
}
__device__ __forceinline__ float ex2(float x) {
    float r; asm("ex2.approx.f32 %0, %1;" : "=f"(r) : "f"(x)); return r;
}
__device__ __forceinline__ float lg2(float x) {
    float r; asm("lg2.approx.f32 %0, %1;" : "=f"(r) : "f"(x)); return r;
}

// Two-column GEMV: sLo = sum_i v[i]*ETlo[i], sHi = sum_i v[i]*EThi[i].
// 16 broadcast LDS.128 + 64 FFMA2, 4 accumulators per column.
__device__ __forceinline__ void gemv2(const float* __restrict__ vsrc,
                                      const unsigned long long* __restrict__ ETlo,
                                      const unsigned long long* __restrict__ EThi,
                                      float &sLo, float &sHi) {
    const ulonglong2* ev = reinterpret_cast<const ulonglong2*>(vsrc);
    unsigned long long l0 = 0ull, l1 = 0ull, l2 = 0ull, l3 = 0ull;
    unsigned long long h0 = 0ull, h1 = 0ull, h2 = 0ull, h3 = 0ull;
#pragma unroll
    for (int m = 0; m < 8; m++) {
        const ulonglong2 p = ev[2 * m];
        const ulonglong2 q = ev[2 * m + 1];
        ffma2(l0, p.x, ETlo[4 * m + 0]);
        ffma2(h0, p.x, EThi[4 * m + 0]);
        ffma2(l1, p.y, ETlo[4 * m + 1]);
        ffma2(h1, p.y, EThi[4 * m + 1]);
        ffma2(l2, q.x, ETlo[4 * m + 2]);
        ffma2(h2, q.x, EThi[4 * m + 2]);
        ffma2(l3, q.y, ETlo[4 * m + 3]);
        ffma2(h3, q.y, EThi[4 * m + 3]);
    }
    float a, bq;
    unpack2(fadd2(fadd2(l0, l1), fadd2(l2, l3)), a, bq);
    sLo = a + bq;
    unpack2(fadd2(fadd2(h0, h1), fadd2(h2, h3)), a, bq);
    sHi = a + bq;
}

// SINGLE-WARP GANGS, forward-backward split: 128-thread block = 4 independent
// chains. Warp w: batch 2*bid + (w>>1), direction w&1 (0 fwd, 1 bwd).
// Thread lane owns columns (lane, lane+32); matrix in 64 packed f32x2 regs.
// Sync = __syncwarp only (no cross-warp coupling; all 4 SMSPs busy).
//   fwd: v_t = m_t o (A^T v_{t-1}), t = 1..mid
//   bwd: u_t = m_t o (A u_{t+1}),   t = L-1..mid+1, then beta = A u (no emis.)
//   Z = <v_mid, beta_mid>  -- exact; serial depth 511 -> 256.
// Unroll-2 with exact power-of-2 rescale on step A only (validated r7-r10).
__global__ __launch_bounds__(128) void crf_fb(
    const float* __restrict__ inputs,   // [B, T, N]
    const float* __restrict__ trans,    // [N, N]
    const int*   __restrict__ tags,     // [B, T]
    const int*   __restrict__ lens,     // [B]
    float*       __restrict__ out)      // [B + N*N]
{
    const int bid  = blockIdx.x;
    const int tid  = threadIdx.x;
    const int wid  = tid >> 5;
    const int lane = tid & 31;
    const int bb   = 2 * bid + (wid >> 1);   // my batch
    const int dir  = wid & 1;                // 0 = forward, 1 = backward

    __shared__ __align__(16) float V[4][2][68];   // [warp][buf][vec]
    __shared__ float Rsh[4];
    __shared__ float redD[4];
    __shared__ float redS[4];

    // Passthrough copy of transition_params: 256 blocks x 4 float4 = 4096.
    if (tid < 4) {
        const int idx = bid * 4 + tid;
        reinterpret_cast<float4*>(out + B_)[idx] =
            reinterpret_cast<const float4*>(trans)[idx];
    }

    // Register matrices for my two owned columns, packed over contraction i:
    //  fwd: ET*[m] = exp2(trans[2m..][col] * L2E)  (A^T columns lane, lane+32)
    //  bwd: ET*[m] = exp2(trans[col][2m..] * L2E)  (A rows lane, lane+32)
    unsigned long long ETlo[32], EThi[32];
#pragma unroll
    for (int m = 0; m < 32; m++) {
        const int iaL = dir ? (lane * N_ + 2 * m)       : ((2 * m) * N_ + lane);
        const int ibL = dir ? (lane * N_ + 2 * m + 1)   : ((2 * m + 1) * N_ + lane);
        const int iaH = dir ? ((lane + 32) * N_ + 2 * m)     : ((2 * m) * N_ + lane + 32);
        const int ibH = dir ? ((lane + 32) * N_ + 2 * m + 1) : ((2 * m + 1) * N_ + lane + 32);
        ETlo[m] = pack2(ex2(trans[iaL] * L2E), ex2(trans[ibL] * L2E));
        EThi[m] = pack2(ex2(trans[iaH] * L2E), ex2(trans[ibH] * L2E));
    }

    const float* emit = inputs + (size_t)bb * T_ * N_;
    const int len = lens[bb];
    const int L = (len > 1) ? (len - 1) : 0;   // last alpha index
    const int fsteps = L >> 1;                 // forward GEMV count (mid)
    const int ns = dir ? (L - fsteps) : fsteps;   // my GEMV count
    const int ne = dir ? (ns - 1) : ns;        // last k with a real emission
    const int st = dir ? L : 0;                // emission row at k=0
    const int dr = dir ? -1 : 1;               // row direction

    float (*Vw)[68] = V[wid];

    // Init vector into Vw[0] (+ my accumulated log2 shift R).
    float R;
    if (dir == 0) {
        const float r0 = __ldg(&emit[0]) * L2E;
        R = r0;
        Vw[0][lane]      = ex2(fmaf(emit[lane], L2E, -r0));
        Vw[0][lane + 32] = ex2(fmaf(emit[lane + 32], L2E, -r0));
    } else if (ns > 0) {
        const size_t o = (size_t)L * N_;
        const float r0 = __ldg(&emit[o]) * L2E;
        R = r0;
        Vw[0][lane]      = ex2(fmaf(emit[o + lane], L2E, -r0));
        Vw[0][lane + 32] = ex2(fmaf(emit[o + lane + 32], L2E, -r0));
    } else {
        R = 0.0f;
        Vw[0][lane]      = 1.0f;               // beta = ones when no bwd steps
        Vw[0][lane + 32] = 1.0f;
    }

    // Emission prefetch for both columns, one unrolled pair ahead.
    float eAl = 0.f, eAh = 0.f, eBl = 0.f, eBh = 0.f;
    if (1 <= ne) { const int r = (st + dr) * N_;     eAl = emit[r + lane]; eAh = emit[r + lane + 32]; }
    if (2 <= ne) { const int r = (st + 2 * dr) * N_; eBl = emit[r + lane]; eBh = emit[r + lane + 32]; }

    __syncwarp();

    int k = 1;
    for (; k + 1 <= ns; k += 2) {
        float nAl = 0.f, nAh = 0.f, nBl = 0.f, nBh = 0.f;
        if (k + 2 <= ne) { const int r = (st + dr * (k + 2)) * N_; nAl = emit[r + lane]; nAh = emit[r + lane + 32]; }
        if (k + 3 <= ne) { const int r = (st + dr * (k + 3)) * N_; nBl = emit[r + lane]; nBh = emit[r + lane + 32]; }

        // ---- step A (rescaled, exact power-of-2 shift): Vw[0] -> Vw[1] ----
        {
            const float E0 = Vw[0][0];
            const float q = (float)((int)((__float_as_uint(E0) >> 23) & 0xFF) - 121);
            float sLo, sHi;
            gemv2(&Vw[0][0], ETlo, EThi, sLo, sHi);
            const float msL = ex2(fmaf(eAl, L2E, -q));
            const float msH = ex2(fmaf(eAh, L2E, -q));
            R += q;
            Vw[1][lane]      = msL * sLo;
            Vw[1][lane + 32] = msH * sHi;
            __syncwarp();
        }

        // ---- step B (no rescale): Vw[1] -> Vw[0] ----
        {
            float sLo, sHi;
            gemv2(&Vw[1][0], ETlo, EThi, sLo, sHi);
            const float msL = ex2(eBl * L2E);
            const float msH = ex2(eBh * L2E);
            Vw[0][lane]      = msL * sLo;
            Vw[0][lane + 32] = msH * sHi;
            __syncwarp();
        }

        eAl = nAl; eAh = nAh; eBl = nBl; eBh = nBh;
    }

    // Odd leftover step (k == ns): rescaled, Vw[0] -> Vw[1].
    if (k <= ns) {
        const float E0 = Vw[0][0];
        const float q = (float)((int)((__float_as_uint(E0) >> 23) & 0xFF) - 121);
        float sLo, sHi;
        gemv2(&Vw[0][0], ETlo, EThi, sLo, sHi);
        const float msL = ex2(fmaf(eAl, L2E, -q));
        const float msH = ex2(fmaf(eAh, L2E, -q));
        R += q;
        Vw[1][lane]      = msL * sLo;
        Vw[1][lane + 32] = msH * sHi;
        __syncwarp();
    }

    // ---- join: per batch p (threads [64p, 64p+64)): Z = <v_mid, beta_mid> ----
    if (lane == 0) Rsh[wid] = R;
    __syncthreads();

    const int p  = tid >> 6;                   // which of my block's 2 batches
    const int pt = tid & 63;
    const int bB = 2 * bid + p;
    const int lenB = lens[bB];
    const int LB = (lenB > 1) ? (lenB - 1) : 0;
    const int fsB = LB >> 1;
    const int fpar = fsB & 1;
    const int bpar = (LB - fsB) & 1;

    float dv = V[2 * p][fpar][pt] * V[2 * p + 1][bpar][pt];
#pragma unroll
    for (int off = 16; off; off >>= 1)
        dv += __shfl_xor_sync(0xffffffffu, dv, off);
    if (lane == 0) redD[wid] = dv;

    // Sequence score for batch bB, strided over its 64 threads.
    const float* emitB = inputs + (size_t)bB * T_ * N_;
    const int* btagsB = tags + bB * T_;
    float sc = 0.0f;
    for (int q = pt; q < lenB; q += 64)
        sc += emitB[q * N_ + btagsB[q]];
    for (int q = pt + 1; q < lenB; q += 64)
        sc += trans[btagsB[q - 1] * N_ + btagsB[q]];
#pragma unroll
    for (int off = 16; off; off >>= 1)
        sc += __shfl_xor_sync(0xffffffffu, sc, off);
    if (lane == 0) redS[wid] = sc;
    __syncthreads();

    if (pt == 0) {                             // tid 0 and tid 64
        const float logZ =
            (Rsh[2 * p] + Rsh[2 * p + 1] + lg2(redD[2 * p] + redD[2 * p + 1])) * LN2;
        out[bB] = (redS[2 * p] + redS[2 * p + 1]) - logZ;
    }
}

extern "C" void kernel_launch(void* const* d_in, const int* in_sizes, int n_in,
                              void* d_out, int out_size) {
    const float* inputs = (const float*)d_in[0];   // [512, 512, 64] f32
    const float* trans  = (const float*)d_in[1];   // [64, 64] f32
    const int*   tags   = (const int*)d_in[2];     // [512, 512] i32
    const int*   lens   = (const int*)d_in[3];     // [512] i32
    float*       out    = (float*)d_out;           // [512 + 4096] f32

    crf_fb<<<B_ / 2, 128>>>(inputs, trans, tags, lens, out);
}